// round 8
// baseline (speedup 1.0000x reference)
#include <cuda_runtime.h>
#include <cuda_fp16.h>
#include <mma.h>
#include <cstdint>

using namespace nvcuda;

// ---------------- problem constants ----------------
#define B_   4
#define T_   4096
#define DIN  1024
#define H_   16
#define D_   64
#define NCOL 2048            // H*D*2
#define BT   (B_*T_)         // 16384
#define BH   (B_*H_)         // 64
#define CH   128
#define NC   (T_/CH)         // 32

// ---------------- GEMM tile config (round-3 proven) ----------------
#define MT   128             // rows per CTA (= one scan chunk)
#define NTILE 128            // cols per CTA = one head
#define KC   64              // k per stage
#define NSTG (DIN/KC)        // 16
#define PAD  24              // row stride = 88 halves = 176B (16B aligned)
#define LDS_ (KC + PAD)      // 88
#define TILE_BYTES (MT * LDS_ * 2)      // 22528
#define STAGE_BYTES (2 * TILE_BYTES)    // A + W = 45056
#define SM_Q_OFF   (2 * STAGE_BYTES)    // 90112
#define SM_PEU_OFF (SM_Q_OFF + 256)     // 90368: 128 floats of p
#define SM_RED_OFF (SM_PEU_OFF + 512)   // 90880: 4x64 partials
#define SMEM_TOTAL (SM_RED_OFF + 1024)  // 91904
#define CLD  132             // epilogue C row stride (floats)

// ---------------- device scratch ----------------
__device__ __half g_Ah[BT * DIN];
__device__ __half g_Wt[NCOL * DIN];   // transposed: [n][k]
__device__ float g_ev[BH * T_ * D_];
__device__ float g_eu[BH * T_];
__device__ float g_csev[BH * NC * D_];   // RAW chunk sums (prefix done in k45)
__device__ float g_cseu[BH * NC];

// ---------------- helpers ----------------
__device__ __forceinline__ uint32_t smem_u32(const void* p) {
    uint32_t a;
    asm("{ .reg .u64 t; cvta.to.shared.u64 t, %1; cvt.u32.u64 %0, t; }" : "=r"(a) : "l"(p));
    return a;
}
#define CP_ASYNC16(dst, src) \
    asm volatile("cp.async.ca.shared.global [%0], [%1], 16;" :: "r"(dst), "l"(src))
#define CP_COMMIT() asm volatile("cp.async.commit_group;" ::: "memory")
#define CP_WAIT1()  asm volatile("cp.async.wait_group 1;" ::: "memory")
#define CP_WAIT0()  asm volatile("cp.async.wait_group 0;" ::: "memory")

// ---------------------------------------------------------------------------
// K0a: convert A (f32) -> fp16
// ---------------------------------------------------------------------------
__global__ void k0_convA(const float* __restrict__ A) {
    int i = (blockIdx.x * 256 + threadIdx.x) * 4;
    float4 v = *(const float4*)(A + i);
    __half2* o = (__half2*)(g_Ah + i);
    o[0] = __floats2half2_rn(v.x, v.y);
    o[1] = __floats2half2_rn(v.z, v.w);
}

// ---------------------------------------------------------------------------
// K0b: transpose + convert W (f32 [DIN][NCOL]) -> fp16 [NCOL][DIN]
// ---------------------------------------------------------------------------
__global__ void k0_convW(const float* __restrict__ W) {
    __shared__ float tile[32][33];
    int n0 = blockIdx.x * 32, k0 = blockIdx.y * 32;
#pragma unroll
    for (int j = 0; j < 32; j += 8)
        tile[threadIdx.y + j][threadIdx.x] = W[(k0 + threadIdx.y + j) * NCOL + n0 + threadIdx.x];
    __syncthreads();
#pragma unroll
    for (int j = 0; j < 32; j += 8) {
        float x = tile[threadIdx.x][threadIdx.y + j];
        g_Wt[(n0 + threadIdx.y + j) * DIN + k0 + threadIdx.x] = __float2half_rn(x);
    }
}

// ---------------------------------------------------------------------------
// K1: wmma fp16 GEMM (128x128 = 1 head x 128 t-rows) + fused epilogue
//     + fused chunk sums (replaces k2). 256 threads, occ=2.
// ---------------------------------------------------------------------------
__global__ void __launch_bounds__(256, 2) k1_mma(const float* __restrict__ Q) {
    extern __shared__ char smem[];
    const uint32_t sb = smem_u32(smem);
    const int tid = threadIdx.x;
    const int wid = tid >> 5;
    const int h = blockIdx.x;             // head
    const int mtile = blockIdx.y;         // 0..127
    const int rowBase = mtile * MT;
    const int nBase = h * NTILE;

    float* qs = (float*)(smem + SM_Q_OFF);
    if (tid < 64) qs[tid] = Q[h * 64 + tid];

    const int warp_m = wid & 1;
    const int warp_n = wid >> 1;

    wmma::fragment<wmma::accumulator, 16, 16, 16, float> acc[4][2];
#pragma unroll
    for (int i = 0; i < 4; i++)
#pragma unroll
        for (int j = 0; j < 2; j++) wmma::fill_fragment(acc[i][j], 0.f);

    const int r_ = tid >> 3;
    const int c_ = tid & 7;
    auto issue_stage = [&](int sbuf, int k0) {
        const uint32_t stg = sb + sbuf * STAGE_BYTES;
#pragma unroll
        for (int rep = 0; rep < 4; rep++) {
            const int r = r_ + rep * 32;
            const uint32_t so = (uint32_t)((r * LDS_ + c_ * 8) * 2);
            CP_ASYNC16(stg + so, g_Ah + (rowBase + r) * DIN + k0 + c_ * 8);
            CP_ASYNC16(stg + TILE_BYTES + so, g_Wt + (nBase + r) * DIN + k0 + c_ * 8);
        }
        CP_COMMIT();
    };

    issue_stage(0, 0);
    issue_stage(1, KC);

    for (int it = 0; it < NSTG; it++) {
        if (it >= NSTG - 2) { CP_WAIT0(); } else { CP_WAIT1(); }
        __syncthreads();
        const __half* As = (const __half*)(smem + (it & 1) * STAGE_BYTES);
        const __half* Ws = (const __half*)(smem + (it & 1) * STAGE_BYTES + TILE_BYTES);

#pragma unroll
        for (int ks = 0; ks < KC / 16; ks++) {
            wmma::fragment<wmma::matrix_a, 16, 16, 16, __half, wmma::row_major> af[4];
            wmma::fragment<wmma::matrix_b, 16, 16, 16, __half, wmma::col_major> bf[2];
#pragma unroll
            for (int i = 0; i < 4; i++)
                wmma::load_matrix_sync(af[i], As + (warp_m * 64 + i * 16) * LDS_ + ks * 16, LDS_);
#pragma unroll
            for (int j = 0; j < 2; j++)
                wmma::load_matrix_sync(bf[j], Ws + (warp_n * 32 + j * 16) * LDS_ + ks * 16, LDS_);
#pragma unroll
            for (int i = 0; i < 4; i++)
#pragma unroll
                for (int j = 0; j < 2; j++)
                    wmma::mma_sync(acc[i][j], af[i], bf[j], acc[i][j]);
        }
        __syncthreads();
        if (it + 2 < NSTG) issue_stage(it & 1, (it + 2) * KC);
    }

    // ---- store accumulators to smem C [128][CLD] ----
    float* Cs = (float*)smem;
#pragma unroll
    for (int i = 0; i < 4; i++)
#pragma unroll
        for (int j = 0; j < 2; j++)
            wmma::store_matrix_sync(Cs + (warp_m * 64 + i * 16) * CLD + warp_n * 32 + j * 16,
                                    acc[i][j], CLD, wmma::mem_row_major);
    __syncthreads();

    // ---- fused epilogue: thread = (row, d-half) ----
    float* peu = (float*)(smem + SM_PEU_OFF);
    {
        const int row = tid >> 1;
        const int half = tid & 1;          // d in [half*32, half*32+32)
        const int gRow = rowBase + row;
        const int b = gRow >> 12, t = gRow & 4095;
        float* crow = Cs + row * CLD + half * 64;
        const float* q = qs + half * 32;

        float sp = 0.f;
        float vv[32];
#pragma unroll
        for (int d = 0; d < 32; d++) {
            float2 kv = *(const float2*)(crow + 2 * d);
            sp = fmaf(q[d], fmaxf(kv.x, 0.f), sp);
            vv[d] = fmaxf(kv.y, 0.f);
        }
        sp += __shfl_xor_sync(0xffffffffu, sp, 1);
        const float p = __expf(sp);
        const int base = (b * H_ + h) * T_ + t;
        if (half == 0) { g_eu[base] = p; peu[row] = p; }
        float4* dst = (float4*)(g_ev + base * 64 + half * 32);
#pragma unroll
        for (int i = 0; i < 8; i++)
            dst[i] = make_float4(p * vv[4 * i], p * vv[4 * i + 1],
                                 p * vv[4 * i + 2], p * vv[4 * i + 3]);
        // write p*v back into the v slots for the chunk-sum reduction
#pragma unroll
        for (int d = 0; d < 32; d++) crow[2 * d + 1] = p * vv[d];
    }
    __syncthreads();

    // ---- chunk sums (replaces k2): this CTA's 128 rows = chunk c of batch b ----
    {
        const int b = rowBase >> 12;
        const int c = (rowBase >> 7) & (NC - 1);
        const int bh = b * H_ + h;
        float* sred = (float*)(smem + SM_RED_OFF);    // [4][64]

        const int d = tid & 63;
        const int qd = tid >> 6;                      // 0..3 -> rows qd*32..+32
        float s = 0.f;
#pragma unroll 8
        for (int r = 0; r < 32; r++)
            s += Cs[(qd * 32 + r) * CLD + 2 * d + 1];
        sred[qd * 64 + d] = s;
        __syncthreads();
        if (tid < 64)
            g_csev[(bh * NC + c) * 64 + tid] =
                sred[tid] + sred[64 + tid] + sred[128 + tid] + sred[192 + tid];
        else if (tid < 96) {
            // eu chunk sum: warp 2 reduces peu[0..127]
            const int l = tid - 64;
            float su = peu[l] + peu[l + 32] + peu[l + 64] + peu[l + 96];
#pragma unroll
            for (int o = 16; o; o >>= 1) su += __shfl_down_sync(0xffffffffu, su, o);
            if (l == 0) g_cseu[bh * NC + c] = su;
        }
    }
}

// ---------------------------------------------------------------------------
// K45: per-block exclusive prefix over raw chunk sums + cumsum + divide
//      + head-sum -> out.  block = (b, chunk); 1024 threads = (h, d)
// ---------------------------------------------------------------------------
__global__ void __launch_bounds__(1024) k45(float* __restrict__ out) {
    __shared__ float sred[8 * 16 * 64];   // [t_sub][h][d]  32KB
    const int bid = blockIdx.x;
    const int b = bid >> 5;
    const int c = bid & (NC - 1);
    const int tid = threadIdx.x;
    const int h = tid >> 6;
    const int d = tid & 63;
    const int bh = b * H_ + h;

    // exclusive prefix of raw chunk sums (replaces k3)
    float accw = 0.f, accu = 0.f;
    for (int cp = 0; cp < c; cp++) {
        accw += g_csev[(bh * NC + cp) * 64 + d];
        accu += g_cseu[bh * NC + cp];
    }

    const float* evp = g_ev + (bh * T_ + c * CH) * 64 + d;
    const float* eup = g_eu + bh * T_ + c * CH;
    float* outp = out + (b * T_ + c * CH) * 64;

    for (int tb = 0; tb < 16; tb++) {
#pragma unroll
        for (int j = 0; j < 8; j++) {
            const int t = tb * 8 + j;
            accu += eup[t];
            accw += evp[t * 64];
            sred[(j * 16 + h) * 64 + d] = __fdividef(accw, accu);
        }
        __syncthreads();
        if (tid < 512) {
            const int ts = tid >> 6, d2 = tid & 63;
            float s = 0.f;
#pragma unroll
            for (int hh = 0; hh < 16; hh++) s += sred[(ts * 16 + hh) * 64 + d2];
            outp[(tb * 8 + ts) * 64 + d2] = s;
        }
        __syncthreads();
    }
}

// ---------------------------------------------------------------------------
extern "C" void kernel_launch(void* const* d_in, const int* in_sizes, int n_in,
                              void* d_out, int out_size) {
    const float* A = (const float*)d_in[0];   // inputs   [4,4096,1024]
    const float* W = (const float*)d_in[1];   // kv_kernel[1024,16,64,2]
    const float* Q = (const float*)d_in[2];   // q_kernel [16,64]
    float* out = (float*)d_out;

    cudaFuncSetAttribute(k1_mma, cudaFuncAttributeMaxDynamicSharedMemorySize, SMEM_TOTAL);

    k0_convA<<<BT * DIN / 1024, 256>>>(A);
    k0_convW<<<dim3(NCOL / 32, DIN / 32), dim3(32, 8)>>>(W);
    k1_mma<<<dim3(H_, BT / MT), 256, SMEM_TOTAL>>>(Q);
    k45<<<B_ * NC, 1024>>>(out);
}

// round 10
// speedup vs baseline: 1.5217x; 1.5217x over previous
#include <cuda_runtime.h>
#include <cuda_fp16.h>
#include <mma.h>
#include <cstdint>

using namespace nvcuda;

// ---------------- problem constants ----------------
#define B_   4
#define T_   4096
#define DIN  1024
#define H_   16
#define D_   64
#define NCOL 2048            // H*D*2
#define BT   (B_*T_)         // 16384
#define BH   (B_*H_)         // 64
#define CH   128
#define NC   (T_/CH)         // 32

// ---------------- GEMM tile config (round-3 proven) ----------------
#define MT   128             // rows per CTA
#define NTILE 128            // cols per CTA = one head
#define KC   64              // k per stage
#define NSTG (DIN/KC)        // 16
#define PAD  24              // row stride = 88 halves = 176B (16B aligned)
#define LDS_ (KC + PAD)      // 88
#define TILE_BYTES (MT * LDS_ * 2)      // 22528
#define STAGE_BYTES (2 * TILE_BYTES)    // A + W = 45056
#define SM_Q_OFF   (2 * STAGE_BYTES)    // 90112
#define SMEM_TOTAL (SM_Q_OFF + 512)     // 90624
#define CLD  132             // epilogue C row stride (floats)

// ---------------- device scratch ----------------
__device__ __half g_Ah[BT * DIN];
__device__ __half g_Wt[NCOL * DIN];   // transposed: [n][k]
__device__ float g_ev[BH * T_ * D_];
__device__ float g_eu[BH * T_];
__device__ float g_csev[BH * NC * D_];   // RAW chunk sums (prefix done in k45)
__device__ float g_cseu[BH * NC];

// ---------------- helpers ----------------
__device__ __forceinline__ uint32_t smem_u32(const void* p) {
    uint32_t a;
    asm("{ .reg .u64 t; cvta.to.shared.u64 t, %1; cvt.u32.u64 %0, t; }" : "=r"(a) : "l"(p));
    return a;
}
#define CP_ASYNC16(dst, src) \
    asm volatile("cp.async.ca.shared.global [%0], [%1], 16;" :: "r"(dst), "l"(src))
#define CP_COMMIT() asm volatile("cp.async.commit_group;" ::: "memory")
#define CP_WAIT1()  asm volatile("cp.async.wait_group 1;" ::: "memory")
#define CP_WAIT0()  asm volatile("cp.async.wait_group 0;" ::: "memory")

// ---------------------------------------------------------------------------
// K0a: convert A (f32) -> fp16
// ---------------------------------------------------------------------------
__global__ void k0_convA(const float* __restrict__ A) {
    int i = (blockIdx.x * 256 + threadIdx.x) * 4;
    float4 v = *(const float4*)(A + i);
    __half2* o = (__half2*)(g_Ah + i);
    o[0] = __floats2half2_rn(v.x, v.y);
    o[1] = __floats2half2_rn(v.z, v.w);
}

// ---------------------------------------------------------------------------
// K0b: transpose + convert W (f32 [DIN][NCOL]) -> fp16 [NCOL][DIN]
// ---------------------------------------------------------------------------
__global__ void k0_convW(const float* __restrict__ W) {
    __shared__ float tile[32][33];
    int n0 = blockIdx.x * 32, k0 = blockIdx.y * 32;
#pragma unroll
    for (int j = 0; j < 32; j += 8)
        tile[threadIdx.y + j][threadIdx.x] = W[(k0 + threadIdx.y + j) * NCOL + n0 + threadIdx.x];
    __syncthreads();
#pragma unroll
    for (int j = 0; j < 32; j += 8) {
        float x = tile[threadIdx.x][threadIdx.y + j];
        g_Wt[(n0 + threadIdx.y + j) * DIN + k0 + threadIdx.x] = __float2half_rn(x);
    }
}

// ---------------------------------------------------------------------------
// K1: wmma fp16 GEMM (128x128 per CTA = 1 head x 128 t-rows) + fused epilogue
//     (exact round-3/round-5 version: 256 threads, occ=2)
// ---------------------------------------------------------------------------
__global__ void __launch_bounds__(256, 2) k1_mma(const float* __restrict__ Q) {
    extern __shared__ char smem[];
    const uint32_t sb = smem_u32(smem);
    const int tid = threadIdx.x;
    const int wid = tid >> 5;
    const int h = blockIdx.x;             // head
    const int mtile = blockIdx.y;         // 0..127
    const int rowBase = mtile * MT;
    const int nBase = h * NTILE;

    float* qs = (float*)(smem + SM_Q_OFF);
    if (tid < 64) qs[tid] = Q[h * 64 + tid];

    // warp tile: 64(m) x 32(n); warp_m = wid&1, warp_n = wid>>1
    const int warp_m = wid & 1;
    const int warp_n = wid >> 1;

    wmma::fragment<wmma::accumulator, 16, 16, 16, float> acc[4][2];
#pragma unroll
    for (int i = 0; i < 4; i++)
#pragma unroll
        for (int j = 0; j < 2; j++) wmma::fill_fragment(acc[i][j], 0.f);

    const int r_ = tid >> 3;
    const int c_ = tid & 7;
    auto issue_stage = [&](int sbuf, int k0) {
        const uint32_t stg = sb + sbuf * STAGE_BYTES;
#pragma unroll
        for (int rep = 0; rep < 4; rep++) {
            const int r = r_ + rep * 32;
            const uint32_t so = (uint32_t)((r * LDS_ + c_ * 8) * 2);
            CP_ASYNC16(stg + so, g_Ah + (rowBase + r) * DIN + k0 + c_ * 8);
            CP_ASYNC16(stg + TILE_BYTES + so, g_Wt + (nBase + r) * DIN + k0 + c_ * 8);
        }
        CP_COMMIT();
    };

    issue_stage(0, 0);
    issue_stage(1, KC);

    for (int it = 0; it < NSTG; it++) {
        if (it >= NSTG - 2) { CP_WAIT0(); } else { CP_WAIT1(); }
        __syncthreads();
        const __half* As = (const __half*)(smem + (it & 1) * STAGE_BYTES);
        const __half* Ws = (const __half*)(smem + (it & 1) * STAGE_BYTES + TILE_BYTES);

#pragma unroll
        for (int ks = 0; ks < KC / 16; ks++) {
            wmma::fragment<wmma::matrix_a, 16, 16, 16, __half, wmma::row_major> af[4];
            wmma::fragment<wmma::matrix_b, 16, 16, 16, __half, wmma::col_major> bf[2];
#pragma unroll
            for (int i = 0; i < 4; i++)
                wmma::load_matrix_sync(af[i], As + (warp_m * 64 + i * 16) * LDS_ + ks * 16, LDS_);
#pragma unroll
            for (int j = 0; j < 2; j++)
                wmma::load_matrix_sync(bf[j], Ws + (warp_n * 32 + j * 16) * LDS_ + ks * 16, LDS_);
#pragma unroll
            for (int i = 0; i < 4; i++)
#pragma unroll
                for (int j = 0; j < 2; j++)
                    wmma::mma_sync(acc[i][j], af[i], bf[j], acc[i][j]);
        }
        __syncthreads();
        if (it + 2 < NSTG) issue_stage(it & 1, (it + 2) * KC);
    }

    // ---- store accumulators to smem C [128][CLD] ----
    float* Cs = (float*)smem;
#pragma unroll
    for (int i = 0; i < 4; i++)
#pragma unroll
        for (int j = 0; j < 2; j++)
            wmma::store_matrix_sync(Cs + (warp_m * 64 + i * 16) * CLD + warp_n * 32 + j * 16,
                                    acc[i][j], CLD, wmma::mem_row_major);
    __syncthreads();

    // ---- fused epilogue: thread = (row, d-half) ----
    {
        const int row = tid >> 1;
        const int half = tid & 1;
        const int gRow = rowBase + row;
        const int b = gRow >> 12, t = gRow & 4095;
        const float* crow = Cs + row * CLD + half * 64;
        const float* q = qs + half * 32;

        float sp = 0.f;
        float vv[32];
#pragma unroll
        for (int d = 0; d < 32; d++) {
            float2 kv = *(const float2*)(crow + 2 * d);
            sp = fmaf(q[d], fmaxf(kv.x, 0.f), sp);
            vv[d] = fmaxf(kv.y, 0.f);
        }
        sp += __shfl_xor_sync(0xffffffffu, sp, 1);
        const float p = __expf(sp);
        const int base = (b * H_ + h) * T_ + t;
        if (half == 0) g_eu[base] = p;
        float4* dst = (float4*)(g_ev + base * 64 + half * 32);
#pragma unroll
        for (int i = 0; i < 8; i++)
            dst[i] = make_float4(p * vv[4 * i], p * vv[4 * i + 1],
                                 p * vv[4 * i + 2], p * vv[4 * i + 3]);
    }
}

// ---------------------------------------------------------------------------
// K2: per-chunk RAW sums; 256-thread blocks, 4 chunks/block (round-5 proven)
// ---------------------------------------------------------------------------
__global__ void __launch_bounds__(256) k2_chunksum() {
    __shared__ float sred[4][64];
    const int slice = threadIdx.x >> 6;     // 0..3
    const int tid2  = threadIdx.x & 63;     // d
    const int idx = blockIdx.x * 4 + slice; // bh*NC + c
    const int bh = idx >> 5;
    const int c  = idx & (NC - 1);

    const float* evp = g_ev + (bh * T_ + c * CH) * 64;
    float s = 0.f;
#pragma unroll 8
    for (int t = 0; t < CH; t++) s += evp[t * 64 + tid2];
    g_csev[(bh * NC + c) * 64 + tid2] = s;

    const float* eup = g_eu + bh * T_ + c * CH;
    sred[slice][tid2] = eup[tid2] + eup[tid2 + 64];
    __syncthreads();
    if (tid2 < 32) {
        float v2 = sred[slice][tid2] + sred[slice][tid2 + 32];
#pragma unroll
        for (int o = 16; o; o >>= 1) v2 += __shfl_down_sync(0xffffffffu, v2, o);
        if (tid2 == 0) g_cseu[bh * NC + c] = v2;
    }
}

// ---------------------------------------------------------------------------
// K45: per-block prefix of raw chunk sums + cumsum + divide + head-sum -> out
//      NEW: grid = (b, chunk, d-half) = 256 blocks; 512 threads = (h, d32);
//      16-t phases (8 rounds, 16 syncs), store phase uses ALL threads.
// ---------------------------------------------------------------------------
__global__ void __launch_bounds__(512) k45(float* __restrict__ out) {
    __shared__ float sred[16 * 16 * 32];   // [t_sub][h][d32]  32KB
    const int bid = blockIdx.x;
    const int dhalf = bid & 1;
    const int c = (bid >> 1) & (NC - 1);
    const int b = bid >> 6;
    const int tid = threadIdx.x;
    const int h = tid >> 5;            // 0..15
    const int d32 = tid & 31;
    const int bh = b * H_ + h;

    // exclusive prefix of raw chunk sums
    float accw = 0.f, accu = 0.f;
    for (int cp = 0; cp < c; cp++) {
        accw += g_csev[(bh * NC + cp) * 64 + dhalf * 32 + d32];
        accu += g_cseu[bh * NC + cp];
    }

    const float* evp = g_ev + (bh * T_ + c * CH) * 64 + dhalf * 32 + d32;
    const float* eup = g_eu + bh * T_ + c * CH;
    float* outp = out + (b * T_ + c * CH) * 64 + dhalf * 32;

    for (int tb = 0; tb < 8; tb++) {
#pragma unroll
        for (int j = 0; j < 16; j++) {
            const int t = tb * 16 + j;
            accu += eup[t];
            accw += evp[t * 64];
            sred[(j * 16 + h) * 32 + d32] = __fdividef(accw, accu);
        }
        __syncthreads();
        {
            const int ts = tid >> 5;       // 0..15
            const int d2 = tid & 31;
            float s = 0.f;
#pragma unroll
            for (int hh = 0; hh < 16; hh++) s += sred[(ts * 16 + hh) * 32 + d2];
            outp[(tb * 16 + ts) * 64 + d2] = s;
        }
        __syncthreads();
    }
}

// ---------------------------------------------------------------------------
extern "C" void kernel_launch(void* const* d_in, const int* in_sizes, int n_in,
                              void* d_out, int out_size) {
    const float* A = (const float*)d_in[0];   // inputs   [4,4096,1024]
    const float* W = (const float*)d_in[1];   // kv_kernel[1024,16,64,2]
    const float* Q = (const float*)d_in[2];   // q_kernel [16,64]
    float* out = (float*)d_out;

    cudaFuncSetAttribute(k1_mma, cudaFuncAttributeMaxDynamicSharedMemorySize, SMEM_TOTAL);

    k0_convA<<<BT * DIN / 1024, 256>>>(A);
    k0_convW<<<dim3(NCOL / 32, DIN / 32), dim3(32, 8)>>>(W);
    k1_mma<<<dim3(H_, BT / MT), 256, SMEM_TOTAL>>>(Q);
    k2_chunksum<<<BH * NC / 4, 256>>>();
    k45<<<B_ * NC * 2, 512>>>(out);
}

// round 14
// speedup vs baseline: 1.5776x; 1.0367x over previous
#include <cuda_runtime.h>
#include <cuda_fp16.h>
#include <cstdint>

// ---------------- problem constants ----------------
#define B_   4
#define T_   4096
#define DIN  1024
#define H_   16
#define D_   64
#define NCOL 2048            // H*D*2
#define BT   (B_*T_)         // 16384
#define BH   (B_*H_)         // 64
#define CH   128
#define NC   (T_/CH)         // 32

// ---------------- GEMM tile config ----------------
#define MT   128             // rows per CTA
#define NTILE 128            // cols per CTA = one head
#define KC   64              // k halves per stage
#define NSTG (DIN/KC)        // 16
#define PAD  24
#define LDS_ (KC + PAD)      // 88 halves = 176B row stride (conflict-free ldmatrix)
#define TILE_BYTES (MT * LDS_ * 2)      // 22528
#define STAGE_BYTES (2 * TILE_BYTES)    // A + W = 45056
#define SM_Q_OFF   (2 * STAGE_BYTES)    // 90112
#define SM_SPP_OFF (SM_Q_OFF + 256)     // 90368
#define SMEM_TOTAL (SM_SPP_OFF + 1024)  // 91392

// ---------------- device scratch ----------------
__device__ __half g_Ah[BT * DIN];
__device__ __half g_Wt[NCOL * DIN];   // transposed: [n][k]
__device__ float g_ev[BH * T_ * D_];
__device__ float g_eu[BH * T_];
__device__ float g_csev[BH * NC * D_];   // RAW chunk sums
__device__ float g_cseu[BH * NC];

// ---------------- helpers ----------------
__device__ __forceinline__ uint32_t smem_u32(const void* p) {
    uint32_t a;
    asm("{ .reg .u64 t; cvta.to.shared.u64 t, %1; cvt.u32.u64 %0, t; }" : "=r"(a) : "l"(p));
    return a;
}
#define CP_ASYNC16(dst, src) \
    asm volatile("cp.async.ca.shared.global [%0], [%1], 16;" :: "r"(dst), "l"(src))
#define CP_COMMIT() asm volatile("cp.async.commit_group;" ::: "memory")
#define CP_WAIT1()  asm volatile("cp.async.wait_group 1;" ::: "memory")
#define CP_WAIT0()  asm volatile("cp.async.wait_group 0;" ::: "memory")

#define LDSM4(r, addr) \
    asm volatile("ldmatrix.sync.aligned.m8n8.x4.shared.b16 {%0,%1,%2,%3}, [%4];" \
        : "=r"((r)[0]), "=r"((r)[1]), "=r"((r)[2]), "=r"((r)[3]) : "r"(addr))

#define MMA16816(c, a, b0, b1) \
    asm volatile("mma.sync.aligned.m16n8k16.row.col.f32.f16.f16.f32 " \
        "{%0,%1,%2,%3}, {%4,%5,%6,%7}, {%8,%9}, {%0,%1,%2,%3};" \
        : "+f"((c)[0]), "+f"((c)[1]), "+f"((c)[2]), "+f"((c)[3]) \
        : "r"((a)[0]), "r"((a)[1]), "r"((a)[2]), "r"((a)[3]), "r"(b0), "r"(b1))

// ---------------------------------------------------------------------------
// K0a: convert A (f32) -> fp16
// ---------------------------------------------------------------------------
__global__ void k0_convA(const float* __restrict__ A) {
    int i = (blockIdx.x * 256 + threadIdx.x) * 4;
    float4 v = *(const float4*)(A + i);
    __half2* o = (__half2*)(g_Ah + i);
    o[0] = __floats2half2_rn(v.x, v.y);
    o[1] = __floats2half2_rn(v.z, v.w);
}

// ---------------------------------------------------------------------------
// K0b: transpose + convert W (f32 [DIN][NCOL]) -> fp16 [NCOL][DIN]
// ---------------------------------------------------------------------------
__global__ void k0_convW(const float* __restrict__ W) {
    __shared__ float tile[32][33];
    int n0 = blockIdx.x * 32, k0 = blockIdx.y * 32;
#pragma unroll
    for (int j = 0; j < 32; j += 8)
        tile[threadIdx.y + j][threadIdx.x] = W[(k0 + threadIdx.y + j) * NCOL + n0 + threadIdx.x];
    __syncthreads();
#pragma unroll
    for (int j = 0; j < 32; j += 8) {
        float x = tile[threadIdx.x][threadIdx.y + j];
        g_Wt[(n0 + threadIdx.y + j) * DIN + k0 + threadIdx.x] = __float2half_rn(x);
    }
}

// ---------------------------------------------------------------------------
// K1: raw mma.sync m16n8k16 GEMM (128x128 per CTA) + in-register epilogue.
//     8 warps = 4(m) x 2(n); warp tile 32(m) x 64(n). 256 threads, occ=2.
// ---------------------------------------------------------------------------
__global__ void __launch_bounds__(256, 2) k1_mma(const float* __restrict__ Q) {
    extern __shared__ char smem[];
    const uint32_t sb = smem_u32(smem);
    const int tid = threadIdx.x;
    const int wid = tid >> 5, lane = tid & 31;
    const int h = blockIdx.x;
    const int mtile = blockIdx.y;
    const int rowBase = mtile * MT;
    const int nBase = h * NTILE;

    float* qs = (float*)(smem + SM_Q_OFF);
    float* spp = (float*)(smem + SM_SPP_OFF);   // [128][2]
    if (tid < 64) qs[tid] = Q[h * 64 + tid];

    const int warp_m = wid & 3;     // 0..3 -> 32 rows each
    const int warp_n = wid >> 2;    // 0..1 -> 64 cols each

    float acc[2][8][4];
#pragma unroll
    for (int mt = 0; mt < 2; mt++)
#pragma unroll
        for (int nt = 0; nt < 8; nt++)
#pragma unroll
            for (int e = 0; e < 4; e++) acc[mt][nt][e] = 0.f;

    // ldmatrix per-lane offsets (bytes within tile)
    const uint32_t lrow = lane & 15;
    const uint32_t lhalf = (lane >> 4) * 8;     // k sub-chunk (halves)
    const uint32_t aoff0 = ((warp_m * 32 + lrow) * LDS_ + lhalf) * 2;
    const uint32_t aoff1 = aoff0 + 16 * LDS_ * 2;
    const uint32_t boffB = ((warp_n * 64 + lrow) * LDS_ + lhalf) * 2;

    // cp.async issue (unchanged skeleton)
    const int r_ = tid >> 3;
    const int c_ = tid & 7;
    auto issue_stage = [&](int sbuf, int k0) {
        const uint32_t stg = sb + sbuf * STAGE_BYTES;
#pragma unroll
        for (int rep = 0; rep < 4; rep++) {
            const int r = r_ + rep * 32;
            const uint32_t so = (uint32_t)((r * LDS_ + c_ * 8) * 2);
            CP_ASYNC16(stg + so, g_Ah + (rowBase + r) * DIN + k0 + c_ * 8);
            CP_ASYNC16(stg + TILE_BYTES + so, g_Wt + (nBase + r) * DIN + k0 + c_ * 8);
        }
        CP_COMMIT();
    };

    issue_stage(0, 0);
    issue_stage(1, KC);

    for (int it = 0; it < NSTG; it++) {
        if (it >= NSTG - 2) { CP_WAIT0(); } else { CP_WAIT1(); }
        __syncthreads();
        const uint32_t aB = sb + (it & 1) * STAGE_BYTES;
        const uint32_t wB = aB + TILE_BYTES;

#pragma unroll
        for (int ks = 0; ks < 4; ks++) {
            const uint32_t ko = ks * 32;      // 16 halves = 32 bytes
            uint32_t a0[4], a1[4], br[4][4];
            LDSM4(a0, aB + aoff0 + ko);
            LDSM4(a1, aB + aoff1 + ko);
#pragma unroll
            for (int nb = 0; nb < 4; nb++)
                LDSM4(br[nb], wB + boffB + nb * (16 * LDS_ * 2) + ko);
#pragma unroll
            for (int nb = 0; nb < 4; nb++) {
                MMA16816(acc[0][2 * nb],     a0, br[nb][0], br[nb][2]);
                MMA16816(acc[0][2 * nb + 1], a0, br[nb][1], br[nb][3]);
                MMA16816(acc[1][2 * nb],     a1, br[nb][0], br[nb][2]);
                MMA16816(acc[1][2 * nb + 1], a1, br[nb][1], br[nb][3]);
            }
        }
        __syncthreads();
        if (it + 2 < NSTG) issue_stage(it & 1, (it + 2) * KC);
    }

    // ---- in-register epilogue ----
    // acc[mt][nt]: c0,c1 = row g cols 2tg,2tg+1 (=(k,v) at d); c2,c3 = row g+8
    const int g = lane >> 2, tg = lane & 3;
    float qv[8];
#pragma unroll
    for (int nt = 0; nt < 8; nt++) qv[nt] = qs[warp_n * 32 + nt * 4 + tg];

#pragma unroll
    for (int mt = 0; mt < 2; mt++) {
        float sp0 = 0.f, sp1 = 0.f;
#pragma unroll
        for (int nt = 0; nt < 8; nt++) {
            sp0 = fmaf(qv[nt], fmaxf(acc[mt][nt][0], 0.f), sp0);
            sp1 = fmaf(qv[nt], fmaxf(acc[mt][nt][2], 0.f), sp1);
        }
        sp0 += __shfl_xor_sync(0xffffffffu, sp0, 1);
        sp0 += __shfl_xor_sync(0xffffffffu, sp0, 2);
        sp1 += __shfl_xor_sync(0xffffffffu, sp1, 1);
        sp1 += __shfl_xor_sync(0xffffffffu, sp1, 2);
        if (tg == 0) {
            spp[(warp_m * 32 + mt * 16 + g) * 2 + warp_n] = sp0;
            spp[(warp_m * 32 + mt * 16 + g + 8) * 2 + warp_n] = sp1;
        }
    }
    __syncthreads();

#pragma unroll
    for (int mt = 0; mt < 2; mt++) {
        const int r0 = warp_m * 32 + mt * 16 + g;
        const int r1 = r0 + 8;
        const float p0 = __expf(spp[r0 * 2] + spp[r0 * 2 + 1]);
        const float p1 = __expf(spp[r1 * 2] + spp[r1 * 2 + 1]);
        const int gR0 = rowBase + r0, gR1 = rowBase + r1;
        const int base0 = ((gR0 >> 12) * H_ + h) * T_ + (gR0 & 4095);
        const int base1 = ((gR1 >> 12) * H_ + h) * T_ + (gR1 & 4095);
        if (tg == 0 && warp_n == 0) { g_eu[base0] = p0; g_eu[base1] = p1; }
#pragma unroll
        for (int nt = 0; nt < 8; nt++) {
            const int dcol = warp_n * 32 + nt * 4 + tg;
            g_ev[base0 * 64 + dcol] = p0 * fmaxf(acc[mt][nt][1], 0.f);
            g_ev[base1 * 64 + dcol] = p1 * fmaxf(acc[mt][nt][3], 0.f);
        }
    }
}

// ---------------------------------------------------------------------------
// K2: per-chunk RAW sums (round-5 proven)
// ---------------------------------------------------------------------------
__global__ void __launch_bounds__(256) k2_chunksum() {
    __shared__ float sred[4][64];
    const int slice = threadIdx.x >> 6;
    const int tid2  = threadIdx.x & 63;
    const int idx = blockIdx.x * 4 + slice;
    const int bh = idx >> 5;
    const int c  = idx & (NC - 1);

    const float* evp = g_ev + (bh * T_ + c * CH) * 64;
    float s = 0.f;
#pragma unroll 8
    for (int t = 0; t < CH; t++) s += evp[t * 64 + tid2];
    g_csev[(bh * NC + c) * 64 + tid2] = s;

    const float* eup = g_eu + bh * T_ + c * CH;
    sred[slice][tid2] = eup[tid2] + eup[tid2 + 64];
    __syncthreads();
    if (tid2 < 32) {
        float v2 = sred[slice][tid2] + sred[slice][tid2 + 32];
#pragma unroll
        for (int o = 16; o; o >>= 1) v2 += __shfl_down_sync(0xffffffffu, v2, o);
        if (tid2 == 0) g_cseu[bh * NC + c] = v2;
    }
}

// ---------------------------------------------------------------------------
// K45: prefix + cumsum + divide + head-sum (round-9 proven split version)
// ---------------------------------------------------------------------------
__global__ void __launch_bounds__(512) k45(float* __restrict__ out) {
    __shared__ float sred[16 * 16 * 32];
    const int bid = blockIdx.x;
    const int dhalf = bid & 1;
    const int c = (bid >> 1) & (NC - 1);
    const int b = bid >> 6;
    const int tid = threadIdx.x;
    const int h = tid >> 5;
    const int d32 = tid & 31;
    const int bh = b * H_ + h;

    float accw = 0.f, accu = 0.f;
    for (int cp = 0; cp < c; cp++) {
        accw += g_csev[(bh * NC + cp) * 64 + dhalf * 32 + d32];
        accu += g_cseu[bh * NC + cp];
    }

    const float* evp = g_ev + (bh * T_ + c * CH) * 64 + dhalf * 32 + d32;
    const float* eup = g_eu + bh * T_ + c * CH;
    float* outp = out + (b * T_ + c * CH) * 64 + dhalf * 32;

    for (int tb = 0; tb < 8; tb++) {
#pragma unroll
        for (int j = 0; j < 16; j++) {
            const int t = tb * 16 + j;
            accu += eup[t];
            accw += evp[t * 64];
            sred[(j * 16 + h) * 32 + d32] = __fdividef(accw, accu);
        }
        __syncthreads();
        {
            const int ts = tid >> 5;
            const int d2 = tid & 31;
            float s = 0.f;
#pragma unroll
            for (int hh = 0; hh < 16; hh++) s += sred[(ts * 16 + hh) * 32 + d2];
            outp[(tb * 16 + ts) * 64 + d2] = s;
        }
        __syncthreads();
    }
}

// ---------------------------------------------------------------------------
extern "C" void kernel_launch(void* const* d_in, const int* in_sizes, int n_in,
                              void* d_out, int out_size) {
    const float* A = (const float*)d_in[0];   // inputs   [4,4096,1024]
    const float* W = (const float*)d_in[1];   // kv_kernel[1024,16,64,2]
    const float* Q = (const float*)d_in[2];   // q_kernel [16,64]
    float* out = (float*)d_out;

    cudaFuncSetAttribute(k1_mma, cudaFuncAttributeMaxDynamicSharedMemorySize, SMEM_TOTAL);

    k0_convA<<<BT * DIN / 1024, 256>>>(A);
    k0_convW<<<dim3(NCOL / 32, DIN / 32), dim3(32, 8)>>>(W);
    k1_mma<<<dim3(H_, BT / MT), 256, SMEM_TOTAL>>>(Q);
    k2_chunksum<<<BH * NC / 4, 256>>>();
    k45<<<B_ * NC * 2, 512>>>(out);
}

// round 16
// speedup vs baseline: 1.5787x; 1.0007x over previous
#include <cuda_runtime.h>
#include <cuda_fp16.h>
#include <cstdint>

// ---------------- problem constants ----------------
#define B_   4
#define T_   4096
#define DIN  1024
#define H_   16
#define D_   64
#define NCOL 2048            // H*D*2
#define BT   (B_*T_)         // 16384
#define BH   (B_*H_)         // 64
#define CH   128
#define NC   (T_/CH)         // 32

// ---------------- GEMM tile config ----------------
#define MT   128             // rows per CTA (= one scan chunk)
#define NTILE 128            // cols per CTA = one head
#define KC   64              // k halves per stage
#define NSTG (DIN/KC)        // 16
#define PAD  24
#define LDS_ (KC + PAD)      // 88 halves = 176B row stride (conflict-free ldmatrix)
#define TILE_BYTES (MT * LDS_ * 2)      // 22528
#define STAGE_BYTES (2 * TILE_BYTES)    // A + W = 45056
#define SM_Q_OFF   (2 * STAGE_BYTES)    // 90112
#define SM_SPP_OFF (SM_Q_OFF + 256)     // 90368: [128][2] partial dots
#define SM_CS_OFF  (SM_SPP_OFF + 1024)  // 91392: [4][64] csum partials + [4] eu
#define SMEM_TOTAL (SM_CS_OFF + 1024 + 32)  // 92448

// ---------------- device scratch ----------------
__device__ __half g_Ah[BT * DIN];
__device__ __half g_Wt[NCOL * DIN];   // transposed: [n][k]
__device__ float g_ev[BH * T_ * D_];
__device__ float g_eu[BH * T_];
__device__ float g_csev[BH * NC * D_];   // RAW chunk sums (prefix in k45)
__device__ float g_cseu[BH * NC];

// ---------------- helpers ----------------
__device__ __forceinline__ uint32_t smem_u32(const void* p) {
    uint32_t a;
    asm("{ .reg .u64 t; cvta.to.shared.u64 t, %1; cvt.u32.u64 %0, t; }" : "=r"(a) : "l"(p));
    return a;
}
#define CP_ASYNC16(dst, src) \
    asm volatile("cp.async.ca.shared.global [%0], [%1], 16;" :: "r"(dst), "l"(src))
#define CP_COMMIT() asm volatile("cp.async.commit_group;" ::: "memory")
#define CP_WAIT1()  asm volatile("cp.async.wait_group 1;" ::: "memory")
#define CP_WAIT0()  asm volatile("cp.async.wait_group 0;" ::: "memory")

#define LDSM4(r, addr) \
    asm volatile("ldmatrix.sync.aligned.m8n8.x4.shared.b16 {%0,%1,%2,%3}, [%4];" \
        : "=r"((r)[0]), "=r"((r)[1]), "=r"((r)[2]), "=r"((r)[3]) : "r"(addr))

#define MMA16816(c, a, b0, b1) \
    asm volatile("mma.sync.aligned.m16n8k16.row.col.f32.f16.f16.f32 " \
        "{%0,%1,%2,%3}, {%4,%5,%6,%7}, {%8,%9}, {%0,%1,%2,%3};" \
        : "+f"((c)[0]), "+f"((c)[1]), "+f"((c)[2]), "+f"((c)[3]) \
        : "r"((a)[0]), "r"((a)[1]), "r"((a)[2]), "r"((a)[3]), "r"(b0), "r"(b1))

// ---------------------------------------------------------------------------
// K0a: convert A (f32) -> fp16
// ---------------------------------------------------------------------------
__global__ void k0_convA(const float* __restrict__ A) {
    int i = (blockIdx.x * 256 + threadIdx.x) * 4;
    float4 v = *(const float4*)(A + i);
    __half2* o = (__half2*)(g_Ah + i);
    o[0] = __floats2half2_rn(v.x, v.y);
    o[1] = __floats2half2_rn(v.z, v.w);
}

// ---------------------------------------------------------------------------
// K0b: transpose + convert W (f32 [DIN][NCOL]) -> fp16 [NCOL][DIN]
// ---------------------------------------------------------------------------
__global__ void k0_convW(const float* __restrict__ W) {
    __shared__ float tile[32][33];
    int n0 = blockIdx.x * 32, k0 = blockIdx.y * 32;
#pragma unroll
    for (int j = 0; j < 32; j += 8)
        tile[threadIdx.y + j][threadIdx.x] = W[(k0 + threadIdx.y + j) * NCOL + n0 + threadIdx.x];
    __syncthreads();
#pragma unroll
    for (int j = 0; j < 32; j += 8) {
        float x = tile[threadIdx.x][threadIdx.y + j];
        g_Wt[(n0 + threadIdx.y + j) * DIN + k0 + threadIdx.x] = __float2half_rn(x);
    }
}

// ---------------------------------------------------------------------------
// K1: raw mma.sync m16n8k16 GEMM (128x128 per CTA) + in-register epilogue
//     + in-register chunk sums (replaces k2). 256 threads, occ=2.
// ---------------------------------------------------------------------------
__global__ void __launch_bounds__(256, 2) k1_mma(const float* __restrict__ Q) {
    extern __shared__ char smem[];
    const uint32_t sb = smem_u32(smem);
    const int tid = threadIdx.x;
    const int wid = tid >> 5, lane = tid & 31;
    const int h = blockIdx.x;
    const int mtile = blockIdx.y;
    const int rowBase = mtile * MT;
    const int nBase = h * NTILE;

    float* qs = (float*)(smem + SM_Q_OFF);
    float* spp = (float*)(smem + SM_SPP_OFF);   // [128][2]
    if (tid < 64) qs[tid] = Q[h * 64 + tid];

    const int warp_m = wid & 3;     // 0..3 -> 32 rows each
    const int warp_n = wid >> 2;    // 0..1 -> 64 cols each

    float acc[2][8][4];
#pragma unroll
    for (int mt = 0; mt < 2; mt++)
#pragma unroll
        for (int nt = 0; nt < 8; nt++)
#pragma unroll
            for (int e = 0; e < 4; e++) acc[mt][nt][e] = 0.f;

    // ldmatrix per-lane offsets (bytes within tile)
    const uint32_t lrow = lane & 15;
    const uint32_t lhalf = (lane >> 4) * 8;
    const uint32_t aoff0 = ((warp_m * 32 + lrow) * LDS_ + lhalf) * 2;
    const uint32_t aoff1 = aoff0 + 16 * LDS_ * 2;
    const uint32_t boffB = ((warp_n * 64 + lrow) * LDS_ + lhalf) * 2;

    const int r_ = tid >> 3;
    const int c_ = tid & 7;
    auto issue_stage = [&](int sbuf, int k0) {
        const uint32_t stg = sb + sbuf * STAGE_BYTES;
#pragma unroll
        for (int rep = 0; rep < 4; rep++) {
            const int r = r_ + rep * 32;
            const uint32_t so = (uint32_t)((r * LDS_ + c_ * 8) * 2);
            CP_ASYNC16(stg + so, g_Ah + (rowBase + r) * DIN + k0 + c_ * 8);
            CP_ASYNC16(stg + TILE_BYTES + so, g_Wt + (nBase + r) * DIN + k0 + c_ * 8);
        }
        CP_COMMIT();
    };

    issue_stage(0, 0);
    issue_stage(1, KC);

    for (int it = 0; it < NSTG; it++) {
        if (it >= NSTG - 2) { CP_WAIT0(); } else { CP_WAIT1(); }
        __syncthreads();
        const uint32_t aB = sb + (it & 1) * STAGE_BYTES;
        const uint32_t wB = aB + TILE_BYTES;

#pragma unroll
        for (int ks = 0; ks < 4; ks++) {
            const uint32_t ko = ks * 32;
            uint32_t a0[4], a1[4], br[4][4];
            LDSM4(a0, aB + aoff0 + ko);
            LDSM4(a1, aB + aoff1 + ko);
#pragma unroll
            for (int nb = 0; nb < 4; nb++)
                LDSM4(br[nb], wB + boffB + nb * (16 * LDS_ * 2) + ko);
#pragma unroll
            for (int nb = 0; nb < 4; nb++) {
                MMA16816(acc[0][2 * nb],     a0, br[nb][0], br[nb][2]);
                MMA16816(acc[0][2 * nb + 1], a0, br[nb][1], br[nb][3]);
                MMA16816(acc[1][2 * nb],     a1, br[nb][0], br[nb][2]);
                MMA16816(acc[1][2 * nb + 1], a1, br[nb][1], br[nb][3]);
            }
        }
        __syncthreads();
        if (it + 2 < NSTG) issue_stage(it & 1, (it + 2) * KC);
    }

    // ---- in-register epilogue ----
    // acc[mt][nt]: c0,c1 = row g cols (k,v at d); c2,c3 = row g+8
    const int g = lane >> 2, tg = lane & 3;
    float qv[8];
#pragma unroll
    for (int nt = 0; nt < 8; nt++) qv[nt] = qs[warp_n * 32 + nt * 4 + tg];

#pragma unroll
    for (int mt = 0; mt < 2; mt++) {
        float sp0 = 0.f, sp1 = 0.f;
#pragma unroll
        for (int nt = 0; nt < 8; nt++) {
            sp0 = fmaf(qv[nt], fmaxf(acc[mt][nt][0], 0.f), sp0);
            sp1 = fmaf(qv[nt], fmaxf(acc[mt][nt][2], 0.f), sp1);
        }
        sp0 += __shfl_xor_sync(0xffffffffu, sp0, 1);
        sp0 += __shfl_xor_sync(0xffffffffu, sp0, 2);
        sp1 += __shfl_xor_sync(0xffffffffu, sp1, 1);
        sp1 += __shfl_xor_sync(0xffffffffu, sp1, 2);
        if (tg == 0) {
            spp[(warp_m * 32 + mt * 16 + g) * 2 + warp_n] = sp0;
            spp[(warp_m * 32 + mt * 16 + g + 8) * 2 + warp_n] = sp1;
        }
    }
    __syncthreads();

    // second pass: p, stores, and per-column chunk-sum accumulation
    float csum[8];
#pragma unroll
    for (int nt = 0; nt < 8; nt++) csum[nt] = 0.f;
    float eusum = 0.f;

#pragma unroll
    for (int mt = 0; mt < 2; mt++) {
        const int r0 = warp_m * 32 + mt * 16 + g;
        const int r1 = r0 + 8;
        const float p0 = __expf(spp[r0 * 2] + spp[r0 * 2 + 1]);
        const float p1 = __expf(spp[r1 * 2] + spp[r1 * 2 + 1]);
        const int gR0 = rowBase + r0, gR1 = rowBase + r1;
        const int base0 = ((gR0 >> 12) * H_ + h) * T_ + (gR0 & 4095);
        const int base1 = ((gR1 >> 12) * H_ + h) * T_ + (gR1 & 4095);
        if (tg == 0 && warp_n == 0) { g_eu[base0] = p0; g_eu[base1] = p1; }
        eusum += p0 + p1;
#pragma unroll
        for (int nt = 0; nt < 8; nt++) {
            const int dcol = warp_n * 32 + nt * 4 + tg;
            const float e0 = p0 * fmaxf(acc[mt][nt][1], 0.f);
            const float e1 = p1 * fmaxf(acc[mt][nt][3], 0.f);
            g_ev[base0 * 64 + dcol] = e0;
            g_ev[base1 * 64 + dcol] = e1;
            csum[nt] += e0 + e1;
        }
    }

    // reduce csum over g (lanes differ in bits 2..4), butterfly
#pragma unroll
    for (int nt = 0; nt < 8; nt++) {
        csum[nt] += __shfl_xor_sync(0xffffffffu, csum[nt], 4);
        csum[nt] += __shfl_xor_sync(0xffffffffu, csum[nt], 8);
        csum[nt] += __shfl_xor_sync(0xffffffffu, csum[nt], 16);
    }
    eusum += __shfl_xor_sync(0xffffffffu, eusum, 4);
    eusum += __shfl_xor_sync(0xffffffffu, eusum, 8);
    eusum += __shfl_xor_sync(0xffffffffu, eusum, 16);

    float* cs  = (float*)(smem + SM_CS_OFF);          // [4][64]
    float* ceu = (float*)(smem + SM_CS_OFF + 1024);   // [4]
    if (lane < 4) {   // g==0, tg=lane
#pragma unroll
        for (int nt = 0; nt < 8; nt++)
            cs[warp_m * 64 + warp_n * 32 + nt * 4 + lane] = csum[nt];
    }
    if (lane == 0 && warp_n == 0) ceu[warp_m] = eusum;
    __syncthreads();

    {
        const int b = rowBase >> 12;
        const int c = (rowBase >> 7) & (NC - 1);
        const int bh = b * H_ + h;
        if (tid < 64)
            g_csev[(bh * NC + c) * 64 + tid] =
                cs[tid] + cs[64 + tid] + cs[128 + tid] + cs[192 + tid];
        else if (tid == 64)
            g_cseu[bh * NC + c] = ceu[0] + ceu[1] + ceu[2] + ceu[3];
    }
}

// ---------------------------------------------------------------------------
// K45: prefix + cumsum + divide + head-sum (proven split version)
// ---------------------------------------------------------------------------
__global__ void __launch_bounds__(512) k45(float* __restrict__ out) {
    __shared__ float sred[16 * 16 * 32];
    const int bid = blockIdx.x;
    const int dhalf = bid & 1;
    const int c = (bid >> 1) & (NC - 1);
    const int b = bid >> 6;
    const int tid = threadIdx.x;
    const int h = tid >> 5;
    const int d32 = tid & 31;
    const int bh = b * H_ + h;

    float accw = 0.f, accu = 0.f;
    for (int cp = 0; cp < c; cp++) {
        accw += g_csev[(bh * NC + cp) * 64 + dhalf * 32 + d32];
        accu += g_cseu[bh * NC + cp];
    }

    const float* evp = g_ev + (bh * T_ + c * CH) * 64 + dhalf * 32 + d32;
    const float* eup = g_eu + bh * T_ + c * CH;
    float* outp = out + (b * T_ + c * CH) * 64 + dhalf * 32;

    for (int tb = 0; tb < 8; tb++) {
#pragma unroll
        for (int j = 0; j < 16; j++) {
            const int t = tb * 16 + j;
            accu += eup[t];
            accw += evp[t * 64];
            sred[(j * 16 + h) * 32 + d32] = __fdividef(accw, accu);
        }
        __syncthreads();
        {
            const int ts = tid >> 5;
            const int d2 = tid & 31;
            float s = 0.f;
#pragma unroll
            for (int hh = 0; hh < 16; hh++) s += sred[(ts * 16 + hh) * 32 + d2];
            outp[(tb * 16 + ts) * 64 + d2] = s;
        }
        __syncthreads();
    }
}

// ---------------------------------------------------------------------------
extern "C" void kernel_launch(void* const* d_in, const int* in_sizes, int n_in,
                              void* d_out, int out_size) {
    const float* A = (const float*)d_in[0];   // inputs   [4,4096,1024]
    const float* W = (const float*)d_in[1];   // kv_kernel[1024,16,64,2]
    const float* Q = (const float*)d_in[2];   // q_kernel [16,64]
    float* out = (float*)d_out;

    cudaFuncSetAttribute(k1_mma, cudaFuncAttributeMaxDynamicSharedMemorySize, SMEM_TOTAL);

    k0_convA<<<BT * DIN / 1024, 256>>>(A);
    k0_convW<<<dim3(NCOL / 32, DIN / 32), dim3(32, 8)>>>(W);
    k1_mma<<<dim3(H_, BT / MT), 256, SMEM_TOTAL>>>(Q);
    k45<<<B_ * NC * 2, 512>>>(out);
}